// round 14
// baseline (speedup 1.0000x reference)
#include <cuda_runtime.h>
#include <cuda_bf16.h>
#include <math.h>
#include <stdint.h>

#define BATCH 8
#define SEQ   2048
#define DIM   512
#define MTOT  (BATCH*SEQ)   // 16384

// ---------------------------------------------------------------------------
// Device scratch (allocation-free rule: __device__ globals)
// ---------------------------------------------------------------------------
__device__ __nv_bfloat16 g_xh[MTOT * DIM];
__device__ __nv_bfloat16 g_Wqt_h[DIM * DIM];
__device__ __nv_bfloat16 g_Wkt_h[DIM * DIM];
__device__ __nv_bfloat16 g_Wvt_h[DIM * DIM];
__device__ __nv_bfloat16 g_Qh[MTOT * DIM];
__device__ __nv_bfloat16 g_Kh[MTOT * DIM];
__device__ __nv_bfloat16 g_Vth[MTOT * DIM];                     // [B][DIM][SEQ]
__device__ __nv_bfloat16 g_Ph[(size_t)BATCH * SEQ * SEQ];       // unnormalized exp
__device__ float         g_rpart[(size_t)MTOT * 32];            // partial row sums
__device__ float         g_rinv[MTOT];                          // 1/rowsum

// ---------------------------------------------------------------------------
// Baseline-ISA helpers: ldmatrix / mma.sync / cp.async  (no 'a' features)
// ---------------------------------------------------------------------------
__device__ __forceinline__ uint32_t smem_to_u32(const void* p) {
    uint32_t a;
    asm("{ .reg .u64 t; cvta.to.shared.u64 t, %1; cvt.u32.u64 %0, t; }" : "=r"(a) : "l"(p));
    return a;
}
__device__ __forceinline__ void ldsm4(uint32_t* r, uint32_t addr) {
    asm volatile("ldmatrix.sync.aligned.m8n8.x4.shared.b16 {%0,%1,%2,%3}, [%4];"
                 : "=r"(r[0]), "=r"(r[1]), "=r"(r[2]), "=r"(r[3]) : "r"(addr));
}
__device__ __forceinline__ void mma_bf16(float* c, const uint32_t* a,
                                         uint32_t b0, uint32_t b1) {
    asm volatile("mma.sync.aligned.m16n8k16.row.col.f32.bf16.bf16.f32 "
                 "{%0,%1,%2,%3}, {%4,%5,%6,%7}, {%8,%9}, {%0,%1,%2,%3};"
                 : "+f"(c[0]), "+f"(c[1]), "+f"(c[2]), "+f"(c[3])
                 : "r"(a[0]), "r"(a[1]), "r"(a[2]), "r"(a[3]), "r"(b0), "r"(b1));
}
__device__ __forceinline__ void cp16(uint32_t dst, const void* src) {
    asm volatile("cp.async.cg.shared.global [%0], [%1], 16;" :: "r"(dst), "l"(src));
}
#define CP_COMMIT() asm volatile("cp.async.commit_group;" ::: "memory")
#define CP_WAIT1()  asm volatile("cp.async.wait_group 1;" ::: "memory")

// ---------------------------------------------------------------------------
// 1-term bf16 HMMA GEMM mainloop. Block tile 128x128, BK=64, 4 warps (2Mx2N)
// of 64x64 tiles, 3-stage cp.async pipeline, single __syncthreads per chunk.
// 128B rows, 8-way XOR swizzle (16B-group = ch ^ (row&7)).
// Register double-buffered fragments: ldsm for ks+1 issued before mma of ks.
// ---------------------------------------------------------------------------
#define T_B    (128 * 128)                 // 16384 B per tile
#define STAGEB (2 * T_B)                   // 32768 B
#define NSTAGE 3
#define GEMM_DSMEM (NSTAGE * STAGEB + 128) // +128 alignment slack

__device__ __forceinline__ void gemm_mainloop(uint32_t sbRaw,
    const __nv_bfloat16* pA, const __nv_bfloat16* pB,
    int lda, int ldb, int K, int t, int wm, int wn, int lane,
    float acc[4][8][4])
{
    const uint32_t sb = (sbRaw + 127u) & ~127u;    // 128B-aligned stage base
    const int nc = K / 64;

    // --- cp.async geometry (i-invariant swizzle; r = r0 + 16i) ---
    const int r0 = t >> 3, ch = t & 7;
    const uint32_t dst0 = (uint32_t)r0 * 128u + (uint32_t)(((ch ^ (r0 & 7)) & 7) << 4);
    const __nv_bfloat16* srcA = pA + (size_t)r0 * lda + ch * 8;
    const __nv_bfloat16* srcB = pB + (size_t)r0 * ldb + ch * 8;
    const size_t stepA = (size_t)16 * lda;
    const size_t stepB = (size_t)16 * ldb;

#define ISSUE(sAddr, k0)                                                     \
    do {                                                                     \
        const uint32_t _d = (sAddr) + dst0;                                  \
        const __nv_bfloat16* _sa = srcA + (k0);                              \
        const __nv_bfloat16* _sb2 = srcB + (k0);                             \
        _Pragma("unroll")                                                    \
        for (int _i = 0; _i < 8; _i++)                                       \
            cp16(_d + _i * 2048, _sa + _i * stepA);                          \
        _Pragma("unroll")                                                    \
        for (int _i = 0; _i < 8; _i++)                                       \
            cp16(_d + T_B + _i * 2048, _sb2 + _i * stepB);                   \
    } while (0)

    ISSUE(sb, 0);           CP_COMMIT();
    ISSUE(sb + STAGEB, 64); CP_COMMIT();

    // --- ldmatrix geometry (mi-invariant swizzle; chunk enters via XOR) ---
    const int lrow = lane & 15;
    const int cS   = (lane >> 4) & 1;
    const uint32_t aBase = (uint32_t)(wm * 64 + lrow) * 128u + (uint32_t)((lrow & 7) << 4);
    const uint32_t bBase = (uint32_t)(wn * 64 + lrow) * 128u + (uint32_t)((lrow & 7) << 4)
                           + (uint32_t)T_B;

    uint32_t ah[2][4][4], qh[2][4][4];

#define LOAD_FRAGS(buf, st, ks)                                              \
    do {                                                                     \
        const uint32_t _cx = (uint32_t)((((ks) * 2) + cS) << 4);             \
        _Pragma("unroll")                                                    \
        for (int _mi = 0; _mi < 4; _mi++)                                    \
            ldsm4(ah[buf][_mi], (st) + ((aBase + _mi * 2048u) ^ _cx));       \
        _Pragma("unroll")                                                    \
        for (int _g = 0; _g < 4; _g++)                                       \
            ldsm4(qh[buf][_g], (st) + ((bBase + _g * 2048u) ^ _cx));         \
    } while (0)

    for (int c = 0; c < nc; c++) {
        CP_WAIT1();
        __syncthreads();
        if (c + 2 < nc)
            ISSUE(sb + ((c + 2) % NSTAGE) * STAGEB, (c + 2) * 64);
        CP_COMMIT();

        const uint32_t st = sb + (c % NSTAGE) * STAGEB;
        LOAD_FRAGS(0, st, 0);
        #pragma unroll
        for (int ks = 0; ks < 4; ks++) {
            const int cur = ks & 1;
            if (ks < 3) LOAD_FRAGS(cur ^ 1, st, ks + 1);
            #pragma unroll
            for (int g = 0; g < 4; g++)
                #pragma unroll
                for (int mi = 0; mi < 4; mi++) {
                    mma_bf16(acc[mi][2*g],   ah[cur][mi], qh[cur][g][0], qh[cur][g][2]);
                    mma_bf16(acc[mi][2*g+1], ah[cur][mi], qh[cur][g][1], qh[cur][g][3]);
                }
        }
    }
#undef ISSUE
#undef LOAD_FRAGS
}

#define ZERO_ACC(acc)                                                \
    _Pragma("unroll")                                                \
    for (int mi = 0; mi < 4; mi++)                                   \
        _Pragma("unroll")                                            \
        for (int ni = 0; ni < 8; ni++)                               \
            _Pragma("unroll")                                        \
            for (int r = 0; r < 4; r++) acc[mi][ni][r] = 0.0f;

// ---------------------------------------------------------------------------
// Merged QKV projection: grid.z selects (W, bias, output) triple.
// out = relu(x W + b) -> bf16. Q,K row-major; V written TRANSPOSED to g_Vth.
// ---------------------------------------------------------------------------
__global__ __launch_bounds__(128, 2)
void proj_gemm(const float* __restrict__ bq, const float* __restrict__ bk,
               const float* __restrict__ bv)
{
    extern __shared__ char smem[];
    const uint32_t sb = smem_to_u32(smem);
    const int t = threadIdx.x, wid = t >> 5, lane = t & 31;
    const int wm = wid >> 1, wn = wid & 1;

    const int z = blockIdx.z;                 // 0=Q 1=K 2=V
    const int rowBase = blockIdx.y * 128;
    const int colBase = blockIdx.x * 128;

    const __nv_bfloat16* pA = g_xh + (size_t)rowBase * DIM;
    const __nv_bfloat16* Wh = (z == 0) ? g_Wqt_h : (z == 1) ? g_Wkt_h : g_Wvt_h;
    const float* bias = (z == 0) ? bq : (z == 1) ? bk : bv;
    const __nv_bfloat16* pB = Wh + (size_t)colBase * DIM;

    float acc[4][8][4];
    ZERO_ACC(acc)
    gemm_mainloop(sb, pA, pB, DIM, DIM, DIM, t, wm, wn, lane, acc);

    #pragma unroll
    for (int mi = 0; mi < 4; mi++)
        #pragma unroll
        for (int rr = 0; rr < 2; rr++) {
            const int r = rowBase + wm * 64 + mi * 16 + rr * 8 + (lane >> 2);
            #pragma unroll
            for (int ni = 0; ni < 8; ni++) {
                const int cc = colBase + wn * 64 + ni * 8 + (lane & 3) * 2;
                float a = acc[mi][ni][rr * 2 + 0] + bias[cc];
                float b = acc[mi][ni][rr * 2 + 1] + bias[cc + 1];
                a = fmaxf(a, 0.0f); b = fmaxf(b, 0.0f);
                if (z < 2) {
                    __nv_bfloat16* Ch = (z == 0) ? g_Qh : g_Kh;
                    *(__nv_bfloat162*)(Ch + (size_t)r * DIM + cc) =
                        __halves2bfloat162(__float2bfloat16(a), __float2bfloat16(b));
                } else {
                    // V transposed: g_Vth[b][d][s], b = r>>11, s = r&2047, d = cc
                    const int bb = r >> 11, ss = r & (SEQ - 1);
                    __nv_bfloat16* vt = g_Vth + (size_t)bb * DIM * SEQ + ss;
                    vt[(size_t)cc * SEQ]       = __float2bfloat16(a);
                    vt[(size_t)(cc + 1) * SEQ] = __float2bfloat16(b);
                }
            }
        }
}

// ---------------------------------------------------------------------------
// Scores GEMM with fused exp: P~ = exp(scale * Q K^T) (bf16), plus
// deterministic partial row sums in g_rpart[row][ctaX*2+wn].
// ---------------------------------------------------------------------------
__global__ __launch_bounds__(128, 2)
void score_gemm(float scale)
{
    extern __shared__ char smem[];
    const uint32_t sb = smem_to_u32(smem);
    const int t = threadIdx.x, wid = t >> 5, lane = t & 31;
    const int wm = wid >> 1, wn = wid & 1;

    const int z = blockIdx.z;
    const int rowBase = blockIdx.y * 128;
    const int colBase = blockIdx.x * 128;

    const __nv_bfloat16* pA = g_Qh + (size_t)z * SEQ * DIM + (size_t)rowBase * DIM;
    const __nv_bfloat16* pB = g_Kh + (size_t)z * SEQ * DIM + (size_t)colBase * DIM;

    float acc[4][8][4];
    ZERO_ACC(acc)
    gemm_mainloop(sb, pA, pB, DIM, DIM, DIM, t, wm, wn, lane, acc);

    __nv_bfloat16* Ph = g_Ph + (size_t)z * SEQ * SEQ;

    #pragma unroll
    for (int mi = 0; mi < 4; mi++)
        #pragma unroll
        for (int rr = 0; rr < 2; rr++) {
            const int r = rowBase + wm * 64 + mi * 16 + rr * 8 + (lane >> 2);
            float rsum = 0.0f;
            #pragma unroll
            for (int ni = 0; ni < 8; ni++) {
                const int cc = colBase + wn * 64 + ni * 8 + (lane & 3) * 2;
                float ea = __expf(acc[mi][ni][rr * 2 + 0] * scale);
                float eb = __expf(acc[mi][ni][rr * 2 + 1] * scale);
                rsum += ea + eb;
                *(__nv_bfloat162*)(Ph + (size_t)r * SEQ + cc) =
                    __halves2bfloat162(__float2bfloat16(ea), __float2bfloat16(eb));
            }
            rsum += __shfl_xor_sync(0xffffffffu, rsum, 1);
            rsum += __shfl_xor_sync(0xffffffffu, rsum, 2);
            if ((lane & 3) == 0)
                g_rpart[((size_t)z * SEQ + r) * 32 + blockIdx.x * 2 + wn] = rsum;
        }
}

// ---------------------------------------------------------------------------
// Row-sum reduce: g_rinv[row] = 1 / sum(g_rpart[row][0..31])   (deterministic)
// ---------------------------------------------------------------------------
__global__ __launch_bounds__(256)
void rsum_reduce()
{
    const int row = blockIdx.x * 256 + threadIdx.x;
    if (row >= MTOT) return;
    const float* p = g_rpart + (size_t)row * 32;
    float s = 0.0f;
    #pragma unroll
    for (int i = 0; i < 32; i++) s += p[i];
    g_rinv[row] = 1.0f / s;
}

// ---------------------------------------------------------------------------
// PV GEMM (1-term): out = (P~ x Vt^T) * rinv[row]
// ---------------------------------------------------------------------------
__global__ __launch_bounds__(128, 2)
void pv_gemm(float* __restrict__ out)
{
    extern __shared__ char smem[];
    const uint32_t sb = smem_to_u32(smem);
    const int t = threadIdx.x, wid = t >> 5, lane = t & 31;
    const int wm = wid >> 1, wn = wid & 1;

    const int z = blockIdx.z;
    const int rowBase = blockIdx.y * 128;
    const int colBase = blockIdx.x * 128;

    const __nv_bfloat16* pA = g_Ph  + (size_t)z * SEQ * SEQ + (size_t)rowBase * SEQ;
    const __nv_bfloat16* pB = g_Vth + (size_t)z * DIM * SEQ + (size_t)colBase * SEQ;

    float acc[4][8][4];
    ZERO_ACC(acc)
    gemm_mainloop(sb, pA, pB, SEQ, SEQ, SEQ, t, wm, wn, lane, acc);

    #pragma unroll
    for (int mi = 0; mi < 4; mi++)
        #pragma unroll
        for (int rr = 0; rr < 2; rr++) {
            const int r = rowBase + wm * 64 + mi * 16 + rr * 8 + (lane >> 2);
            const float rinv = g_rinv[z * SEQ + r];
            #pragma unroll
            for (int ni = 0; ni < 8; ni++) {
                const int cc = colBase + wn * 64 + ni * 8 + (lane & 3) * 2;
                float a = acc[mi][ni][rr * 2 + 0] * rinv;
                float b = acc[mi][ni][rr * 2 + 1] * rinv;
                *(float2*)(out + (size_t)z * SEQ * DIM + (size_t)r * DIM + cc) =
                    make_float2(a, b);
            }
        }
}

// ---------------------------------------------------------------------------
// fp32 -> bf16 elementwise convert (for x)
// ---------------------------------------------------------------------------
__global__ __launch_bounds__(256)
void conv_f32(const float* __restrict__ in, __nv_bfloat16* __restrict__ oh, size_t n4)
{
    size_t i = (size_t)blockIdx.x * blockDim.x + threadIdx.x;
    if (i >= n4) return;
    float4 v = ((const float4*)in)[i];
    ((__nv_bfloat162*)oh)[2*i] =
        __halves2bfloat162(__float2bfloat16(v.x), __float2bfloat16(v.y));
    ((__nv_bfloat162*)oh)[2*i+1] =
        __halves2bfloat162(__float2bfloat16(v.z), __float2bfloat16(v.w));
}

// ---------------------------------------------------------------------------
// transpose fp32 [D,D] -> bf16 [D,D]^T, merged over 3 weights via grid.z
// ---------------------------------------------------------------------------
__global__ __launch_bounds__(256)
void transpose_w(const float* __restrict__ Wq, const float* __restrict__ Wk,
                 const float* __restrict__ Wv)
{
    __shared__ float tile[32][33];
    const int z = blockIdx.z;
    const float* in = (z == 0) ? Wq : (z == 1) ? Wk : Wv;
    __nv_bfloat16* oh = (z == 0) ? g_Wqt_h : (z == 1) ? g_Wkt_h : g_Wvt_h;
    const int c0 = blockIdx.x * 32, r0 = blockIdx.y * 32;
    const int tx = threadIdx.x & 31, ty = threadIdx.x >> 5;
    #pragma unroll
    for (int i = 0; i < 4; i++)
        tile[ty + i * 8][tx] = in[(size_t)(r0 + ty + i * 8) * DIM + c0 + tx];
    __syncthreads();
    #pragma unroll
    for (int i = 0; i < 4; i++) {
        const int ro = c0 + ty + i * 8;
        oh[(size_t)ro * DIM + r0 + tx] = __float2bfloat16(tile[tx][ty + i * 8]);
    }
}

// ---------------------------------------------------------------------------
extern "C" void kernel_launch(void* const* d_in, const int* in_sizes, int n_in,
                              void* d_out, int out_size)
{
    const float* x  = (const float*)d_in[0];
    const float* Wq = (const float*)d_in[1];
    const float* bq = (const float*)d_in[2];
    const float* Wk = (const float*)d_in[3];
    const float* bk = (const float*)d_in[4];
    const float* Wv = (const float*)d_in[5];
    const float* bv = (const float*)d_in[6];
    float* out = (float*)d_out;

    cudaFuncSetAttribute(proj_gemm,  cudaFuncAttributeMaxDynamicSharedMemorySize, GEMM_DSMEM);
    cudaFuncSetAttribute(score_gemm, cudaFuncAttributeMaxDynamicSharedMemorySize, GEMM_DSMEM);
    cudaFuncSetAttribute(pv_gemm,    cudaFuncAttributeMaxDynamicSharedMemorySize, GEMM_DSMEM);

    __nv_bfloat16 *xh;
    cudaGetSymbolAddress((void**)&xh, g_xh);

    // 1) convert x -> bf16
    {
        size_t n4 = (size_t)MTOT * DIM / 4;
        conv_f32<<<(unsigned)((n4 + 255) / 256), 256>>>(x, xh, n4);
    }
    // 2) transpose weights (merged): W[D,E] -> Wt[E,D] bf16
    {
        dim3 g(DIM / 32, DIM / 32, 3);
        transpose_w<<<g, 256>>>(Wq, Wk, Wv);
    }
    // 3) merged QKV projections (1-term); V written transposed
    {
        dim3 g(DIM / 128, MTOT / 128, 3);
        proj_gemm<<<g, 128, GEMM_DSMEM>>>(bq, bk, bv);
    }
    // 4) P~ = exp(scale * Q K^T) + partial row sums (fused softmax, no max-sub)
    {
        const float scale = 1.0f / sqrtf((float)DIM);
        dim3 g(SEQ / 128, SEQ / 128, BATCH);
        score_gemm<<<g, 128, GEMM_DSMEM>>>(scale);
    }
    // 5) row-sum reduce -> 1/rowsum
    rsum_reduce<<<(MTOT + 255) / 256, 256>>>();

    // 6) out = (P~ V) / rowsum, 1-term PV
    {
        dim3 g(DIM / 128, SEQ / 128, BATCH);
        pv_gemm<<<g, 128, GEMM_DSMEM>>>(out);
    }
}

// round 15
// speedup vs baseline: 1.5565x; 1.5565x over previous
#include <cuda_runtime.h>
#include <cuda_bf16.h>
#include <math.h>
#include <stdint.h>

#define BATCH 8
#define SEQ   2048
#define DIM   512
#define MTOT  (BATCH*SEQ)   // 16384

// ---------------------------------------------------------------------------
// Device scratch (allocation-free rule: __device__ globals)
// ---------------------------------------------------------------------------
__device__ __nv_bfloat16 g_xh[MTOT * DIM];
__device__ __nv_bfloat16 g_Wqt_h[DIM * DIM];
__device__ __nv_bfloat16 g_Wkt_h[DIM * DIM];
__device__ __nv_bfloat16 g_Wvt_h[DIM * DIM];
__device__ __nv_bfloat16 g_Qh[MTOT * DIM];
__device__ __nv_bfloat16 g_Kh[MTOT * DIM];
__device__ __nv_bfloat16 g_Vth[MTOT * DIM];                     // [B][DIM][SEQ]
__device__ __nv_bfloat16 g_Ph[(size_t)BATCH * SEQ * SEQ];       // unnormalized exp
__device__ float         g_rpart[(size_t)MTOT * 64];            // partial row sums
__device__ float         g_rinv[MTOT];                          // 1/rowsum

// ---------------------------------------------------------------------------
// Baseline-ISA helpers: ldmatrix / mma.sync / cp.async  (no 'a' features)
// ---------------------------------------------------------------------------
__device__ __forceinline__ uint32_t smem_to_u32(const void* p) {
    uint32_t a;
    asm("{ .reg .u64 t; cvta.to.shared.u64 t, %1; cvt.u32.u64 %0, t; }" : "=r"(a) : "l"(p));
    return a;
}
__device__ __forceinline__ void ldsm4(uint32_t* r, uint32_t addr) {
    asm volatile("ldmatrix.sync.aligned.m8n8.x4.shared.b16 {%0,%1,%2,%3}, [%4];"
                 : "=r"(r[0]), "=r"(r[1]), "=r"(r[2]), "=r"(r[3]) : "r"(addr));
}
__device__ __forceinline__ void mma_bf16(float* c, const uint32_t* a,
                                         uint32_t b0, uint32_t b1) {
    asm volatile("mma.sync.aligned.m16n8k16.row.col.f32.bf16.bf16.f32 "
                 "{%0,%1,%2,%3}, {%4,%5,%6,%7}, {%8,%9}, {%0,%1,%2,%3};"
                 : "+f"(c[0]), "+f"(c[1]), "+f"(c[2]), "+f"(c[3])
                 : "r"(a[0]), "r"(a[1]), "r"(a[2]), "r"(a[3]), "r"(b0), "r"(b1));
}
__device__ __forceinline__ void cp16(uint32_t dst, const void* src) {
    asm volatile("cp.async.cg.shared.global [%0], [%1], 16;" :: "r"(dst), "l"(src));
}
#define CP_COMMIT() asm volatile("cp.async.commit_group;" ::: "memory")
#define CP_WAIT1()  asm volatile("cp.async.wait_group 1;" ::: "memory")

// ---------------------------------------------------------------------------
// 1-term bf16 HMMA GEMM mainloop. Block tile 128M x 64N, BK=64, 4 warps
// (2Mx2N) of 64x32 tiles, 3-stage cp.async pipeline, single __syncthreads
// per chunk. 128B rows, 8-way XOR swizzle (16B-group = ch ^ (row&7)).
// 72KB smem + ~140 regs -> 3 CTAs/SM (12 warps).
// ---------------------------------------------------------------------------
#define T_A    (128 * 128)                 // 16384 B A tile
#define T_Bb   (64 * 128)                  // 8192 B  B tile
#define STAGEB (T_A + T_Bb)                // 24576 B
#define NSTAGE 3
#define GEMM_DSMEM (NSTAGE * STAGEB + 128) // 73856 B

__device__ __forceinline__ void gemm_mainloop(uint32_t sbRaw,
    const __nv_bfloat16* pA, const __nv_bfloat16* pB,
    int lda, int ldb, int K, int t, int wm, int wn, int lane,
    float acc[4][4][4])
{
    const uint32_t sb = (sbRaw + 127u) & ~127u;    // 128B-aligned stage base
    const int nc = K / 64;

    // --- cp.async geometry (i-invariant swizzle; r = r0 + 16i) ---
    const int r0 = t >> 3, ch = t & 7;
    const uint32_t dst0 = (uint32_t)r0 * 128u + (uint32_t)(((ch ^ (r0 & 7)) & 7) << 4);
    const __nv_bfloat16* srcA = pA + (size_t)r0 * lda + ch * 8;
    const __nv_bfloat16* srcB = pB + (size_t)r0 * ldb + ch * 8;
    const size_t stepA = (size_t)16 * lda;
    const size_t stepB = (size_t)16 * ldb;

#define ISSUE(sAddr, k0)                                                     \
    do {                                                                     \
        const uint32_t _d = (sAddr) + dst0;                                  \
        const __nv_bfloat16* _sa = srcA + (k0);                              \
        const __nv_bfloat16* _sb2 = srcB + (k0);                             \
        _Pragma("unroll")                                                    \
        for (int _i = 0; _i < 8; _i++)                                       \
            cp16(_d + _i * 2048, _sa + _i * stepA);                          \
        _Pragma("unroll")                                                    \
        for (int _i = 0; _i < 4; _i++)                                       \
            cp16(_d + T_A + _i * 2048, _sb2 + _i * stepB);                   \
    } while (0)

    ISSUE(sb, 0);           CP_COMMIT();
    ISSUE(sb + STAGEB, 64); CP_COMMIT();

    // --- ldmatrix geometry (mi-invariant swizzle; chunk enters via XOR) ---
    const int lrow = lane & 15;
    const int cS   = (lane >> 4) & 1;
    const uint32_t aBase = (uint32_t)(wm * 64 + lrow) * 128u + (uint32_t)((lrow & 7) << 4);
    const uint32_t bBase = (uint32_t)(wn * 32 + lrow) * 128u + (uint32_t)((lrow & 7) << 4)
                           + (uint32_t)T_A;

    for (int c = 0; c < nc; c++) {
        CP_WAIT1();
        __syncthreads();
        if (c + 2 < nc)
            ISSUE(sb + ((c + 2) % NSTAGE) * STAGEB, (c + 2) * 64);
        CP_COMMIT();

        const uint32_t st = sb + (c % NSTAGE) * STAGEB;
        #pragma unroll
        for (int ks = 0; ks < 4; ks++) {
            const uint32_t cx = (uint32_t)((ks * 2 + cS) << 4);
            uint32_t ah[4][4];
            #pragma unroll
            for (int mi = 0; mi < 4; mi++)
                ldsm4(ah[mi], st + ((aBase + mi * 2048u) ^ cx));
            #pragma unroll
            for (int g = 0; g < 2; g++) {
                uint32_t qh[4];
                ldsm4(qh, st + ((bBase + g * 2048u) ^ cx));
                #pragma unroll
                for (int mi = 0; mi < 4; mi++) {
                    mma_bf16(acc[mi][2*g],   ah[mi], qh[0], qh[2]);
                    mma_bf16(acc[mi][2*g+1], ah[mi], qh[1], qh[3]);
                }
            }
        }
    }
#undef ISSUE
}

#define ZERO_ACC(acc)                                                \
    _Pragma("unroll")                                                \
    for (int mi = 0; mi < 4; mi++)                                   \
        _Pragma("unroll")                                            \
        for (int ni = 0; ni < 4; ni++)                               \
            _Pragma("unroll")                                        \
            for (int r = 0; r < 4; r++) acc[mi][ni][r] = 0.0f;

// ---------------------------------------------------------------------------
// Merged QKV projection: grid.z selects (W, bias, output) triple.
// out = relu(x W + b) -> bf16. Q,K row-major; V written TRANSPOSED to g_Vth.
// ---------------------------------------------------------------------------
__global__ __launch_bounds__(128, 3)
void proj_gemm(const float* __restrict__ bq, const float* __restrict__ bk,
               const float* __restrict__ bv)
{
    extern __shared__ char smem[];
    const uint32_t sb = smem_to_u32(smem);
    const int t = threadIdx.x, wid = t >> 5, lane = t & 31;
    const int wm = wid >> 1, wn = wid & 1;

    const int z = blockIdx.z;                 // 0=Q 1=K 2=V
    const int rowBase = blockIdx.y * 128;
    const int colBase = blockIdx.x * 64;

    const __nv_bfloat16* pA = g_xh + (size_t)rowBase * DIM;
    const __nv_bfloat16* Wh = (z == 0) ? g_Wqt_h : (z == 1) ? g_Wkt_h : g_Wvt_h;
    const float* bias = (z == 0) ? bq : (z == 1) ? bk : bv;
    const __nv_bfloat16* pB = Wh + (size_t)colBase * DIM;

    float acc[4][4][4];
    ZERO_ACC(acc)
    gemm_mainloop(sb, pA, pB, DIM, DIM, DIM, t, wm, wn, lane, acc);

    #pragma unroll
    for (int mi = 0; mi < 4; mi++)
        #pragma unroll
        for (int rr = 0; rr < 2; rr++) {
            const int r = rowBase + wm * 64 + mi * 16 + rr * 8 + (lane >> 2);
            #pragma unroll
            for (int ni = 0; ni < 4; ni++) {
                const int cc = colBase + wn * 32 + ni * 8 + (lane & 3) * 2;
                float a = acc[mi][ni][rr * 2 + 0] + bias[cc];
                float b = acc[mi][ni][rr * 2 + 1] + bias[cc + 1];
                a = fmaxf(a, 0.0f); b = fmaxf(b, 0.0f);
                if (z < 2) {
                    __nv_bfloat16* Ch = (z == 0) ? g_Qh : g_Kh;
                    *(__nv_bfloat162*)(Ch + (size_t)r * DIM + cc) =
                        __halves2bfloat162(__float2bfloat16(a), __float2bfloat16(b));
                } else {
                    // V transposed: g_Vth[b][d][s], b = r>>11, s = r&2047, d = cc
                    const int bb = r >> 11, ss = r & (SEQ - 1);
                    __nv_bfloat16* vt = g_Vth + (size_t)bb * DIM * SEQ + ss;
                    vt[(size_t)cc * SEQ]       = __float2bfloat16(a);
                    vt[(size_t)(cc + 1) * SEQ] = __float2bfloat16(b);
                }
            }
        }
}

// ---------------------------------------------------------------------------
// Scores GEMM with fused exp: P~ = exp(scale * Q K^T) (bf16), plus
// deterministic partial row sums in g_rpart[row][ctaX*2+wn]  (64 partials).
// ---------------------------------------------------------------------------
__global__ __launch_bounds__(128, 3)
void score_gemm(float scale)
{
    extern __shared__ char smem[];
    const uint32_t sb = smem_to_u32(smem);
    const int t = threadIdx.x, wid = t >> 5, lane = t & 31;
    const int wm = wid >> 1, wn = wid & 1;

    const int z = blockIdx.z;
    const int rowBase = blockIdx.y * 128;
    const int colBase = blockIdx.x * 64;

    const __nv_bfloat16* pA = g_Qh + (size_t)z * SEQ * DIM + (size_t)rowBase * DIM;
    const __nv_bfloat16* pB = g_Kh + (size_t)z * SEQ * DIM + (size_t)colBase * DIM;

    float acc[4][4][4];
    ZERO_ACC(acc)
    gemm_mainloop(sb, pA, pB, DIM, DIM, DIM, t, wm, wn, lane, acc);

    __nv_bfloat16* Ph = g_Ph + (size_t)z * SEQ * SEQ;

    #pragma unroll
    for (int mi = 0; mi < 4; mi++)
        #pragma unroll
        for (int rr = 0; rr < 2; rr++) {
            const int r = rowBase + wm * 64 + mi * 16 + rr * 8 + (lane >> 2);
            float rsum = 0.0f;
            #pragma unroll
            for (int ni = 0; ni < 4; ni++) {
                const int cc = colBase + wn * 32 + ni * 8 + (lane & 3) * 2;
                float ea = __expf(acc[mi][ni][rr * 2 + 0] * scale);
                float eb = __expf(acc[mi][ni][rr * 2 + 1] * scale);
                rsum += ea + eb;
                *(__nv_bfloat162*)(Ph + (size_t)r * SEQ + cc) =
                    __halves2bfloat162(__float2bfloat16(ea), __float2bfloat16(eb));
            }
            rsum += __shfl_xor_sync(0xffffffffu, rsum, 1);
            rsum += __shfl_xor_sync(0xffffffffu, rsum, 2);
            if ((lane & 3) == 0)
                g_rpart[((size_t)z * SEQ + r) * 64 + blockIdx.x * 2 + wn] = rsum;
        }
}

// ---------------------------------------------------------------------------
// Row-sum reduce: g_rinv[row] = 1 / sum(g_rpart[row][0..63])   (deterministic)
// ---------------------------------------------------------------------------
__global__ __launch_bounds__(256)
void rsum_reduce()
{
    const int row = blockIdx.x * 256 + threadIdx.x;
    if (row >= MTOT) return;
    const float* p = g_rpart + (size_t)row * 64;
    float s = 0.0f;
    #pragma unroll
    for (int i = 0; i < 64; i++) s += p[i];
    g_rinv[row] = 1.0f / s;
}

// ---------------------------------------------------------------------------
// PV GEMM (1-term): out = (P~ x Vt^T) * rinv[row]
// ---------------------------------------------------------------------------
__global__ __launch_bounds__(128, 3)
void pv_gemm(float* __restrict__ out)
{
    extern __shared__ char smem[];
    const uint32_t sb = smem_to_u32(smem);
    const int t = threadIdx.x, wid = t >> 5, lane = t & 31;
    const int wm = wid >> 1, wn = wid & 1;

    const int z = blockIdx.z;
    const int rowBase = blockIdx.y * 128;
    const int colBase = blockIdx.x * 64;

    const __nv_bfloat16* pA = g_Ph  + (size_t)z * SEQ * SEQ + (size_t)rowBase * SEQ;
    const __nv_bfloat16* pB = g_Vth + (size_t)z * DIM * SEQ + (size_t)colBase * SEQ;

    float acc[4][4][4];
    ZERO_ACC(acc)
    gemm_mainloop(sb, pA, pB, SEQ, SEQ, SEQ, t, wm, wn, lane, acc);

    #pragma unroll
    for (int mi = 0; mi < 4; mi++)
        #pragma unroll
        for (int rr = 0; rr < 2; rr++) {
            const int r = rowBase + wm * 64 + mi * 16 + rr * 8 + (lane >> 2);
            const float rinv = g_rinv[z * SEQ + r];
            #pragma unroll
            for (int ni = 0; ni < 4; ni++) {
                const int cc = colBase + wn * 32 + ni * 8 + (lane & 3) * 2;
                float a = acc[mi][ni][rr * 2 + 0] * rinv;
                float b = acc[mi][ni][rr * 2 + 1] * rinv;
                *(float2*)(out + (size_t)z * SEQ * DIM + (size_t)r * DIM + cc) =
                    make_float2(a, b);
            }
        }
}

// ---------------------------------------------------------------------------
// fp32 -> bf16 elementwise convert (for x)
// ---------------------------------------------------------------------------
__global__ __launch_bounds__(256)
void conv_f32(const float* __restrict__ in, __nv_bfloat16* __restrict__ oh, size_t n4)
{
    size_t i = (size_t)blockIdx.x * blockDim.x + threadIdx.x;
    if (i >= n4) return;
    float4 v = ((const float4*)in)[i];
    ((__nv_bfloat162*)oh)[2*i] =
        __halves2bfloat162(__float2bfloat16(v.x), __float2bfloat16(v.y));
    ((__nv_bfloat162*)oh)[2*i+1] =
        __halves2bfloat162(__float2bfloat16(v.z), __float2bfloat16(v.w));
}

// ---------------------------------------------------------------------------
// transpose fp32 [D,D] -> bf16 [D,D]^T, merged over 3 weights via grid.z
// ---------------------------------------------------------------------------
__global__ __launch_bounds__(256)
void transpose_w(const float* __restrict__ Wq, const float* __restrict__ Wk,
                 const float* __restrict__ Wv)
{
    __shared__ float tile[32][33];
    const int z = blockIdx.z;
    const float* in = (z == 0) ? Wq : (z == 1) ? Wk : Wv;
    __nv_bfloat16* oh = (z == 0) ? g_Wqt_h : (z == 1) ? g_Wkt_h : g_Wvt_h;
    const int c0 = blockIdx.x * 32, r0 = blockIdx.y * 32;
    const int tx = threadIdx.x & 31, ty = threadIdx.x >> 5;
    #pragma unroll
    for (int i = 0; i < 4; i++)
        tile[ty + i * 8][tx] = in[(size_t)(r0 + ty + i * 8) * DIM + c0 + tx];
    __syncthreads();
    #pragma unroll
    for (int i = 0; i < 4; i++) {
        const int ro = c0 + ty + i * 8;
        oh[(size_t)ro * DIM + r0 + tx] = __float2bfloat16(tile[tx][ty + i * 8]);
    }
}

// ---------------------------------------------------------------------------
extern "C" void kernel_launch(void* const* d_in, const int* in_sizes, int n_in,
                              void* d_out, int out_size)
{
    const float* x  = (const float*)d_in[0];
    const float* Wq = (const float*)d_in[1];
    const float* bq = (const float*)d_in[2];
    const float* Wk = (const float*)d_in[3];
    const float* bk = (const float*)d_in[4];
    const float* Wv = (const float*)d_in[5];
    const float* bv = (const float*)d_in[6];
    float* out = (float*)d_out;

    cudaFuncSetAttribute(proj_gemm,  cudaFuncAttributeMaxDynamicSharedMemorySize, GEMM_DSMEM);
    cudaFuncSetAttribute(score_gemm, cudaFuncAttributeMaxDynamicSharedMemorySize, GEMM_DSMEM);
    cudaFuncSetAttribute(pv_gemm,    cudaFuncAttributeMaxDynamicSharedMemorySize, GEMM_DSMEM);

    __nv_bfloat16 *xh;
    cudaGetSymbolAddress((void**)&xh, g_xh);

    // 1) convert x -> bf16
    {
        size_t n4 = (size_t)MTOT * DIM / 4;
        conv_f32<<<(unsigned)((n4 + 255) / 256), 256>>>(x, xh, n4);
    }
    // 2) transpose weights (merged): W[D,E] -> Wt[E,D] bf16
    {
        dim3 g(DIM / 32, DIM / 32, 3);
        transpose_w<<<g, 256>>>(Wq, Wk, Wv);
    }
    // 3) merged QKV projections (1-term); V written transposed
    {
        dim3 g(DIM / 64, MTOT / 128, 3);
        proj_gemm<<<g, 128, GEMM_DSMEM>>>(bq, bk, bv);
    }
    // 4) P~ = exp(scale * Q K^T) + partial row sums (fused softmax, no max-sub)
    {
        const float scale = 1.0f / sqrtf((float)DIM);
        dim3 g(SEQ / 64, SEQ / 128, BATCH);
        score_gemm<<<g, 128, GEMM_DSMEM>>>(scale);
    }
    // 5) row-sum reduce -> 1/rowsum
    rsum_reduce<<<(MTOT + 255) / 256, 256>>>();

    // 6) out = (P~ V) / rowsum, 1-term PV
    {
        dim3 g(DIM / 64, SEQ / 128, BATCH);
        pv_gemm<<<g, 128, GEMM_DSMEM>>>(out);
    }
}